// round 5
// baseline (speedup 1.0000x reference)
#include <cuda_runtime.h>
#include <math_constants.h>

#define NB 8
#define NPTS 4096
#define KNN 16
#define MPTS (NB * NPTS)
#define CH 32
#define NCLS 40

__device__ float4 g_p4[MPTS];
__device__ int    g_knn[MPTS * KNN];
__device__ float  g_y[MPTS * CH];
__device__ float  g_pool[NB * CH];

__device__ __forceinline__ float safe_norm3(float x, float y, float z) {
    float s = x * x + y * y + z * z;
    return s > 0.f ? sqrtf(s) : 0.f;
}

__device__ __forceinline__ float angle3(float ax, float ay, float az,
                                        float bx, float by, float bz) {
    float cx = ay * bz - az * by;
    float cy = az * bx - ax * bz;
    float cz = ax * by - ay * bx;
    float cn = safe_norm3(cx, cy, cz);
    float d  = ax * bx + ay * by + az * bz;
    bool ok = (cn > 0.f) || (d != 0.f);
    return ok ? atan2f(cn, d) : 0.f;
}

__device__ __forceinline__ unsigned long long pack2(float lo, float hi) {
    unsigned long long r;
    asm("mov.b64 %0, {%1, %2};" : "=l"(r) : "f"(lo), "f"(hi));
    return r;
}
__device__ __forceinline__ unsigned long long fma2(unsigned long long a,
                                                   unsigned long long b,
                                                   unsigned long long c) {
    unsigned long long d;
    asm("fma.rn.f32x2 %0, %1, %2, %3;" : "=l"(d) : "l"(a), "l"(b), "l"(c));
    return d;
}
__device__ __forceinline__ void unpack2(unsigned long long v, float& lo, float& hi) {
    asm("mov.b64 {%0, %1}, %2;" : "=f"(lo), "=f"(hi) : "l"(v));
}

// pos -> (x,y,z,|p|^2); split so knn is the 4th launch (ncu sample slot)
__global__ __launch_bounds__(256) void prep_kernel(const float* __restrict__ pos,
                                                   int base) {
    int i = base + blockIdx.x * 256 + threadIdx.x;
    float x = pos[3 * i + 0], y = pos[3 * i + 1], z = pos[3 * i + 2];
    g_p4[i] = make_float4(x, y, z, x * x + y * y + z * z);
}

__global__ void pool_init_kernel() {
    int t = threadIdx.x;
    if (t < NB * CH) g_pool[t] = 0.f;
}

// ---------------------------------------------------------------------------
// kNN warp-select, packed-pair edition: 2 queries/warp; each lane-half slot
// keeps one of its query's 16 sorted best. Tile is pre-packed pair-SoA so the
// distance math runs as fma.rn.f32x2 (2 candidates per 3 FMA issue slots).
// ---------------------------------------------------------------------------
__global__ __launch_bounds__(256) void knn_kernel() {
    const unsigned FULL = 0xFFFFFFFFu;
    const float INF = CUDART_INF_F;
    int lane = threadIdx.x & 31;
    int warp = threadIdx.x >> 5;
    int half = lane >> 4;
    int lh   = lane & 15;
    int hsh  = half << 4;

    int qbase = blockIdx.x * 16;
    int q     = qbase + warp * 2 + half;
    int batch = blockIdx.x >> 8;
    int my_ql = q & (NPTS - 1);

    // both warp queries live in the same 32-candidate step (qbase 16-aligned)
    int sb = ((qbase + warp * 2) & (NPTS - 1)) & ~31;

    float4 qp = g_p4[q];
    unsigned long long m2x2 = pack2(-2.f * qp.x, -2.f * qp.x);
    unsigned long long m2y2 = pack2(-2.f * qp.y, -2.f * qp.y);
    unsigned long long m2z2 = pack2(-2.f * qp.z, -2.f * qp.z);

    float L  = INF;     // my sorted slot (shifted d2)
    int   LI = 0;
    float tp = INF;     // running 16th best of my half

    const float4* bp = g_p4 + batch * NPTS;
    __shared__ float4 tA[512];   // (x0,x1,y0,y1) per candidate pair
    __shared__ float4 tB[512];   // (z0,z1,w0,w1)

    for (int t = 0; t < NPTS; t += 1024) {
        __syncthreads();
        {   // pack 4 candidates (2 pairs) per thread
            int c = 4 * threadIdx.x;
            float4 c0 = bp[t + c + 0], c1 = bp[t + c + 1];
            float4 c2 = bp[t + c + 2], c3 = bp[t + c + 3];
            tA[2 * threadIdx.x + 0] = make_float4(c0.x, c1.x, c0.y, c1.y);
            tB[2 * threadIdx.x + 0] = make_float4(c0.z, c1.z, c0.w, c1.w);
            tA[2 * threadIdx.x + 1] = make_float4(c2.x, c3.x, c2.y, c3.y);
            tB[2 * threadIdx.x + 1] = make_float4(c2.z, c3.z, c2.w, c3.w);
        }
        __syncthreads();

#pragma unroll 4
        for (int s = 0; s < 32; s++) {
            int base = t + s * 32;                 // batch-local candidate base
            int p    = s * 16 + lh;                // pair slot in tile
            float4 A = tA[p];                      // x01, y01
            float4 B = tB[p];                      // z01, w01
            unsigned long long x01 = pack2(A.x, A.y);
            unsigned long long y01 = pack2(A.z, A.w);
            unsigned long long z01 = pack2(B.x, B.y);
            unsigned long long w01 = pack2(B.z, B.w);
            unsigned long long d01 = fma2(x01, m2x2, fma2(y01, m2y2, fma2(z01, m2z2, w01)));
            float d0, d1;
            unpack2(d01, d0, d1);
            if (base == sb) {                      // rare: step holds a self point
                int cl0 = base + 2 * lh;
                if (cl0 == my_ql)     d0 = INF;
                if (cl0 + 1 == my_ql) d1 = INF;
            }
            unsigned bal0 = __ballot_sync(FULL, d0 < tp);
            unsigned bal1 = __ballot_sync(FULL, d1 < tp);
            if (bal0 | bal1) {
                unsigned hm0 = (bal0 >> hsh) & 0xFFFFu;   // half-uniform masks
                unsigned hm1 = (bal1 >> hsh) & 0xFFFFu;
                do {
                    unsigned comb = hm0 | hm1;
                    int  l     = comb ? (__ffs(comb) - 1) : 0;
                    bool take0 = (hm0 >> l) & 1u;
                    int  src   = hsh + l;
                    float v0 = __shfl_sync(FULL, d0, src);
                    float v1 = __shfl_sync(FULL, d1, src);
                    float v  = take0 ? v0 : v1;
                    if (!comb) v = INF;                    // identity insert
                    int vi = base + 2 * l + (take0 ? 0 : 1);
                    unsigned ble = __ballot_sync(FULL, L <= v);
                    int pos = __popc((ble >> hsh) & 0xFFFFu);
                    float Lup = __shfl_up_sync(FULL, L, 1);
                    int  LIup = __shfl_up_sync(FULL, LI, 1);
                    if (lh == pos)      { L = v;   LI = vi;   }
                    else if (lh > pos)  { L = Lup; LI = LIup; }
                    tp = __shfl_sync(FULL, L, hsh | 15);
                    if (take0) hm0 &= ~(1u << l);
                    else if (comb) hm1 &= ~(1u << l);
                } while (__any_sync(FULL, (hm0 | hm1) != 0));
            }
        }
    }
    g_knn[q * KNN + lh] = batch * NPTS + LI;
}

// ---------------------------------------------------------------------------
// conv1 (+ fused y = w2a[0:32]^T x1 + b2a)
// ---------------------------------------------------------------------------
__global__ __launch_bounds__(256) void conv1_kernel(
    const float* __restrict__ pos, const float* __restrict__ nrm,
    const float* __restrict__ w1a, const float* __restrict__ b1a,
    const float* __restrict__ w1b, const float* __restrict__ b1b,
    const float* __restrict__ w2a, const float* __restrict__ b2a)
{
    __shared__ float4 sf[8][20];
    __shared__ float  sh[8][17][32];
    int warp = threadIdx.x >> 5;
    int lane = threadIdx.x & 31;
    int i    = blockIdx.x * 8 + warp;

    float wa0 = w1a[0 * 32 + lane], wa1 = w1a[1 * 32 + lane];
    float wa2 = w1a[2 * 32 + lane], wa3 = w1a[3 * 32 + lane];
    float ba  = b1a[lane];
    float wb[32];
#pragma unroll
    for (int k = 0; k < 32; k++) wb[k] = w1b[k * 32 + lane];
    float bb = b1b[lane];

    float pix = pos[3 * i + 0], piy = pos[3 * i + 1], piz = pos[3 * i + 2];
    float nix = nrm[3 * i + 0], niy = nrm[3 * i + 1], niz = nrm[3 * i + 2];

    int j = (lane < KNN) ? g_knn[i * KNN + lane] : i;
    float pjx = pos[3 * j + 0], pjy = pos[3 * j + 1], pjz = pos[3 * j + 2];
    float njx = nrm[3 * j + 0], njy = nrm[3 * j + 1], njz = nrm[3 * j + 2];

    float px = pjx - pix, py = pjy - piy, pz = pjz - piz;
    float f0 = safe_norm3(px, py, pz);
    float f1 = angle3(nix, niy, niz, px, py, pz);
    float f2 = angle3(njx, njy, njz, px, py, pz);
    float f3 = angle3(nix, niy, niz, njx, njy, njz);
    if (lane < 17) sf[warp][lane] = make_float4(f0, f1, f2, f3);
    __syncwarp();

    for (int e = 0; e < 17; e++) {
        float4 f = sf[warp][e];
        float h = ba;
        h = fmaf(f.x, wa0, h); h = fmaf(f.y, wa1, h);
        h = fmaf(f.z, wa2, h); h = fmaf(f.w, wa3, h);
        sh[warp][e][lane] = fmaxf(h, 0.f);
    }
    __syncwarp();

    float best = -CUDART_INF_F;
    for (int e = 0; e < 17; e++) {
        float o0 = bb, o1 = 0.f, o2 = 0.f, o3 = 0.f;
        const float4* hv4 = (const float4*)sh[warp][e];
#pragma unroll
        for (int m = 0; m < 8; m++) {
            float4 hv = hv4[m];
            o0 = fmaf(hv.x, wb[4 * m + 0], o0);
            o1 = fmaf(hv.y, wb[4 * m + 1], o1);
            o2 = fmaf(hv.z, wb[4 * m + 2], o2);
            o3 = fmaf(hv.w, wb[4 * m + 3], o3);
        }
        best = fmaxf(best, (o0 + o1) + (o2 + o3));
    }
    float x1v = fmaxf(best, 0.f);

    sh[warp][0][lane] = x1v;
    __syncwarp();
    float w2[32];
#pragma unroll
    for (int k = 0; k < 32; k++) w2[k] = w2a[k * 32 + lane];
    float a0 = b2a[lane], a1 = 0.f, a2 = 0.f, a3 = 0.f;
    const float4* xv4 = (const float4*)sh[warp][0];
#pragma unroll
    for (int m = 0; m < 8; m++) {
        float4 xv = xv4[m];
        a0 = fmaf(xv.x, w2[4 * m + 0], a0);
        a1 = fmaf(xv.y, w2[4 * m + 1], a1);
        a2 = fmaf(xv.z, w2[4 * m + 2], a2);
        a3 = fmaf(xv.w, w2[4 * m + 3], a3);
    }
    g_y[i * CH + lane] = (a0 + a1) + (a2 + a3);
}

// ---------------------------------------------------------------------------
// conv2 (+ fused global max pool)
// ---------------------------------------------------------------------------
__global__ __launch_bounds__(256) void conv2_kernel(
    const float* __restrict__ pos, const float* __restrict__ nrm,
    const float* __restrict__ w2a,
    const float* __restrict__ w2b, const float* __restrict__ b2b)
{
    __shared__ float4 sf[8][20];
    __shared__ int    si[8][20];
    __shared__ float  sh[8][17][32];
    __shared__ float  red[8][32];
    int warp = threadIdx.x >> 5;
    int lane = threadIdx.x & 31;
    int i    = blockIdx.x * 8 + warp;

    float wa32 = w2a[32 * 32 + lane], wa33 = w2a[33 * 32 + lane];
    float wa34 = w2a[34 * 32 + lane], wa35 = w2a[35 * 32 + lane];
    float wb[32];
#pragma unroll
    for (int k = 0; k < 32; k++) wb[k] = w2b[k * 32 + lane];
    float bb = b2b[lane];

    float pix = pos[3 * i + 0], piy = pos[3 * i + 1], piz = pos[3 * i + 2];
    float nix = nrm[3 * i + 0], niy = nrm[3 * i + 1], niz = nrm[3 * i + 2];

    int j = (lane < KNN) ? g_knn[i * KNN + lane] : i;
    float pjx = pos[3 * j + 0], pjy = pos[3 * j + 1], pjz = pos[3 * j + 2];
    float njx = nrm[3 * j + 0], njy = nrm[3 * j + 1], njz = nrm[3 * j + 2];

    float px = pjx - pix, py = pjy - piy, pz = pjz - piz;
    float f0 = safe_norm3(px, py, pz);
    float f1 = angle3(nix, niy, niz, px, py, pz);
    float f2 = angle3(njx, njy, njz, px, py, pz);
    float f3 = angle3(nix, niy, niz, njx, njy, njz);
    if (lane < 17) { sf[warp][lane] = make_float4(f0, f1, f2, f3); si[warp][lane] = j; }
    __syncwarp();

    float yv[17];
#pragma unroll
    for (int e = 0; e < 17; e++)
        yv[e] = g_y[si[warp][e] * CH + lane];

#pragma unroll
    for (int e = 0; e < 17; e++) {
        float4 f = sf[warp][e];
        float h = yv[e];
        h = fmaf(f.x, wa32, h); h = fmaf(f.y, wa33, h);
        h = fmaf(f.z, wa34, h); h = fmaf(f.w, wa35, h);
        sh[warp][e][lane] = fmaxf(h, 0.f);
    }
    __syncwarp();

    float best = -CUDART_INF_F;
    for (int e = 0; e < 17; e++) {
        float o0 = bb, o1 = 0.f, o2 = 0.f, o3 = 0.f;
        const float4* hv4 = (const float4*)sh[warp][e];
#pragma unroll
        for (int m = 0; m < 8; m++) {
            float4 hv = hv4[m];
            o0 = fmaf(hv.x, wb[4 * m + 0], o0);
            o1 = fmaf(hv.y, wb[4 * m + 1], o1);
            o2 = fmaf(hv.z, wb[4 * m + 2], o2);
            o3 = fmaf(hv.w, wb[4 * m + 3], o3);
        }
        best = fmaxf(best, (o0 + o1) + (o2 + o3));
    }
    red[warp][lane] = fmaxf(best, 0.f);
    __syncthreads();

    if (warp == 0) {
        float m = red[0][lane];
#pragma unroll
        for (int r = 1; r < 8; r++) m = fmaxf(m, red[r][lane]);
        int b = (blockIdx.x * 8) >> 12;
        atomicMax((int*)&g_pool[b * CH + lane], __float_as_int(m));
    }
}

__global__ void fc_kernel(const float* __restrict__ wc,
                          const float* __restrict__ bc,
                          float* __restrict__ out) {
    int t = threadIdx.x;
    if (t < NB * NCLS) {
        int b = t / NCLS, o = t % NCLS;
        float acc = bc[o];
#pragma unroll
        for (int c = 0; c < CH; c++)
            acc = fmaf(g_pool[b * CH + c], wc[c * NCLS + o], acc);
        out[t] = acc;
    }
}

extern "C" void kernel_launch(void* const* d_in, const int* in_sizes, int n_in,
                              void* d_out, int out_size) {
    const float* pos = (const float*)d_in[0];
    const float* nrm = (const float*)d_in[1];
    const float* w1a = (const float*)d_in[3];
    const float* b1a = (const float*)d_in[4];
    const float* w1b = (const float*)d_in[5];
    const float* b1b = (const float*)d_in[6];
    const float* w2a = (const float*)d_in[7];
    const float* b2a = (const float*)d_in[8];
    const float* w2b = (const float*)d_in[9];
    const float* b2b = (const float*)d_in[10];
    const float* wc  = (const float*)d_in[11];
    const float* bc  = (const float*)d_in[12];
    float* out = (float*)d_out;

    prep_kernel<<<MPTS / 512, 256>>>(pos, 0);
    prep_kernel<<<MPTS / 512, 256>>>(pos, MPTS / 2);
    pool_init_kernel<<<1, 256>>>();
    knn_kernel<<<MPTS / 16, 256>>>();                 // 4th launch (ncu sample)
    conv1_kernel<<<MPTS / 8, 256>>>(pos, nrm, w1a, b1a, w1b, b1b, w2a, b2a);
    conv2_kernel<<<MPTS / 8, 256>>>(pos, nrm, w2a, w2b, b2b);
    fc_kernel<<<1, 320>>>(wc, bc, out);
}

// round 6
// speedup vs baseline: 1.0730x; 1.0730x over previous
#include <cuda_runtime.h>
#include <math_constants.h>

#define NB 8
#define NPTS 4096
#define KNN 16
#define MPTS (NB * NPTS)
#define CH 32
#define NCLS 40

__device__ float4 g_p4[MPTS];
__device__ int    g_knn[MPTS * KNN];
__device__ float  g_y[MPTS * CH];
__device__ float  g_pool[NB * CH];

__device__ __forceinline__ float safe_norm3(float x, float y, float z) {
    float s = x * x + y * y + z * z;
    return s > 0.f ? sqrtf(s) : 0.f;
}

__device__ __forceinline__ float angle3(float ax, float ay, float az,
                                        float bx, float by, float bz) {
    float cx = ay * bz - az * by;
    float cy = az * bx - ax * bz;
    float cz = ax * by - ay * bx;
    float cn = safe_norm3(cx, cy, cz);
    float d  = ax * bx + ay * by + az * bz;
    bool ok = (cn > 0.f) || (d != 0.f);
    return ok ? atan2f(cn, d) : 0.f;
}

// pos -> (x,y,z,|p|^2); split so knn is the 4th launch (ncu sample slot)
__global__ __launch_bounds__(256) void prep_kernel(const float* __restrict__ pos,
                                                   int base) {
    int i = base + blockIdx.x * 256 + threadIdx.x;
    float x = pos[3 * i + 0], y = pos[3 * i + 1], z = pos[3 * i + 2];
    g_p4[i] = make_float4(x, y, z, x * x + y * y + z * z);
}

__global__ void pool_init_kernel() {
    int t = threadIdx.x;
    if (t < NB * CH) g_pool[t] = 0.f;
}

// ---------------------------------------------------------------------------
// kNN warp-select v3: 2 queries/warp; every lane evaluates a DISTINCT
// candidate against BOTH queries (32 candidates x 2 queries per ballot pair).
// q0's sorted top-16 lives in lanes 0..15, q1's in lanes 16..31; one insert
// round serves one insert per query simultaneously (disjoint lane ranges).
// ---------------------------------------------------------------------------
__global__ __launch_bounds__(256) void knn_kernel() {
    const unsigned FULL = 0xFFFFFFFFu;
    const float INF = CUDART_INF_F;
    int lane = threadIdx.x & 31;
    int warp = threadIdx.x >> 5;
    int half = lane >> 4;
    int lh   = lane & 15;
    int hsh  = half << 4;

    int qbase = blockIdx.x * 16;
    int q0    = qbase + warp * 2;          // even
    int batch = blockIdx.x >> 8;
    int q0l   = q0 & (NPTS - 1);
    int q1l   = q0l + 1;                   // same 32-block as q0l (q0l even)
    int selfb = q0l & ~31;

    float4 p0 = g_p4[q0];
    float4 p1 = g_p4[q0 + 1];
    float m2x0 = -2.f * p0.x, m2y0 = -2.f * p0.y, m2z0 = -2.f * p0.z;
    float m2x1 = -2.f * p1.x, m2y1 = -2.f * p1.y, m2z1 = -2.f * p1.z;

    float L  = INF;      // my slot of my query's sorted top-16 (shifted d2)
    int   LI = 0;
    float tp0 = INF;     // q0's running 16th best (all lanes)
    float tp1 = INF;     // q1's

    const float4* bp = g_p4 + batch * NPTS;
    __shared__ float4 tile[1024];

    for (int t = 0; t < NPTS; t += 1024) {
        __syncthreads();
#pragma unroll
        for (int u = 0; u < 4; u++)
            tile[threadIdx.x + u * 256] = bp[t + threadIdx.x + u * 256];
        __syncthreads();

#pragma unroll 4
        for (int s = 0; s < 32; s++) {
            int base = t + s * 32;                 // batch-local candidate base
            float4 c = tile[s * 32 + lane];
            float d0 = fmaf(c.x, m2x0, fmaf(c.y, m2y0, fmaf(c.z, m2z0, c.w)));
            float d1 = fmaf(c.x, m2x1, fmaf(c.y, m2y1, fmaf(c.z, m2z1, c.w)));
            if (base == selfb) {                   // rare uniform branch
                int cl = base + lane;
                if (cl == q0l) d0 = INF;
                if (cl == q1l) d1 = INF;
            }
            unsigned bal0 = __ballot_sync(FULL, d0 < tp0);
            unsigned bal1 = __ballot_sync(FULL, d1 < tp1);
            while (bal0 | bal1) {
                int s0 = __ffs(bal0) - 1;          // -1 when empty
                int s1 = __ffs(bal1) - 1;
                float v0 = __shfl_sync(FULL, d0, bal0 ? s0 : 0);
                float v1 = __shfl_sync(FULL, d1, bal1 ? s1 : 0);
                float v;
                int   vi;
                if (half) { v = bal1 ? v1 : INF; vi = base + s1; }
                else      { v = bal0 ? v0 : INF; vi = base + s0; }
                unsigned ble = __ballot_sync(FULL, L <= v);
                int pos = __popc((ble >> hsh) & 0xFFFFu);
                float Lup = __shfl_up_sync(FULL, L, 1);
                int  LIup = __shfl_up_sync(FULL, LI, 1);
                if (lh == pos)      { L = v;   LI = vi;   }
                else if (lh > pos)  { L = Lup; LI = LIup; }
                tp0 = __shfl_sync(FULL, L, 15);
                tp1 = __shfl_sync(FULL, L, 31);
                bal0 &= bal0 - 1;                  // clear lowest (no-op at 0)
                bal1 &= bal1 - 1;
            }
        }
    }
    int q = q0 + half;
    g_knn[q * KNN + lh] = batch * NPTS + LI;
}

// ---------------------------------------------------------------------------
// conv1 (+ fused y = w2a[0:32]^T x1 + b2a)
// ---------------------------------------------------------------------------
__global__ __launch_bounds__(256) void conv1_kernel(
    const float* __restrict__ pos, const float* __restrict__ nrm,
    const float* __restrict__ w1a, const float* __restrict__ b1a,
    const float* __restrict__ w1b, const float* __restrict__ b1b,
    const float* __restrict__ w2a, const float* __restrict__ b2a)
{
    __shared__ float4 sf[8][20];
    __shared__ float  sh[8][17][32];
    int warp = threadIdx.x >> 5;
    int lane = threadIdx.x & 31;
    int i    = blockIdx.x * 8 + warp;

    float wa0 = w1a[0 * 32 + lane], wa1 = w1a[1 * 32 + lane];
    float wa2 = w1a[2 * 32 + lane], wa3 = w1a[3 * 32 + lane];
    float ba  = b1a[lane];
    float wb[32];
#pragma unroll
    for (int k = 0; k < 32; k++) wb[k] = w1b[k * 32 + lane];
    float bb = b1b[lane];

    float pix = pos[3 * i + 0], piy = pos[3 * i + 1], piz = pos[3 * i + 2];
    float nix = nrm[3 * i + 0], niy = nrm[3 * i + 1], niz = nrm[3 * i + 2];

    int j = (lane < KNN) ? g_knn[i * KNN + lane] : i;   // lane16 = self loop
    float pjx = pos[3 * j + 0], pjy = pos[3 * j + 1], pjz = pos[3 * j + 2];
    float njx = nrm[3 * j + 0], njy = nrm[3 * j + 1], njz = nrm[3 * j + 2];

    float px = pjx - pix, py = pjy - piy, pz = pjz - piz;
    float f0 = safe_norm3(px, py, pz);
    float f1 = angle3(nix, niy, niz, px, py, pz);
    float f2 = angle3(njx, njy, njz, px, py, pz);
    float f3 = angle3(nix, niy, niz, njx, njy, njz);
    if (lane < 17) sf[warp][lane] = make_float4(f0, f1, f2, f3);
    __syncwarp();

    for (int e = 0; e < 17; e++) {
        float4 f = sf[warp][e];
        float h = ba;
        h = fmaf(f.x, wa0, h); h = fmaf(f.y, wa1, h);
        h = fmaf(f.z, wa2, h); h = fmaf(f.w, wa3, h);
        sh[warp][e][lane] = fmaxf(h, 0.f);
    }
    __syncwarp();

    float best = -CUDART_INF_F;
    for (int e = 0; e < 17; e++) {
        float o0 = bb, o1 = 0.f, o2 = 0.f, o3 = 0.f;
        const float4* hv4 = (const float4*)sh[warp][e];
#pragma unroll
        for (int m = 0; m < 8; m++) {
            float4 hv = hv4[m];
            o0 = fmaf(hv.x, wb[4 * m + 0], o0);
            o1 = fmaf(hv.y, wb[4 * m + 1], o1);
            o2 = fmaf(hv.z, wb[4 * m + 2], o2);
            o3 = fmaf(hv.w, wb[4 * m + 3], o3);
        }
        best = fmaxf(best, (o0 + o1) + (o2 + o3));
    }
    float x1v = fmaxf(best, 0.f);

    sh[warp][0][lane] = x1v;
    __syncwarp();
    float w2[32];
#pragma unroll
    for (int k = 0; k < 32; k++) w2[k] = w2a[k * 32 + lane];
    float a0 = b2a[lane], a1 = 0.f, a2 = 0.f, a3 = 0.f;
    const float4* xv4 = (const float4*)sh[warp][0];
#pragma unroll
    for (int m = 0; m < 8; m++) {
        float4 xv = xv4[m];
        a0 = fmaf(xv.x, w2[4 * m + 0], a0);
        a1 = fmaf(xv.y, w2[4 * m + 1], a1);
        a2 = fmaf(xv.z, w2[4 * m + 2], a2);
        a3 = fmaf(xv.w, w2[4 * m + 3], a3);
    }
    g_y[i * CH + lane] = (a0 + a1) + (a2 + a3);
}

// ---------------------------------------------------------------------------
// conv2 (+ fused global max pool)
// ---------------------------------------------------------------------------
__global__ __launch_bounds__(256) void conv2_kernel(
    const float* __restrict__ pos, const float* __restrict__ nrm,
    const float* __restrict__ w2a,
    const float* __restrict__ w2b, const float* __restrict__ b2b)
{
    __shared__ float4 sf[8][20];
    __shared__ int    si[8][20];
    __shared__ float  sh[8][17][32];
    __shared__ float  red[8][32];
    int warp = threadIdx.x >> 5;
    int lane = threadIdx.x & 31;
    int i    = blockIdx.x * 8 + warp;

    float wa32 = w2a[32 * 32 + lane], wa33 = w2a[33 * 32 + lane];
    float wa34 = w2a[34 * 32 + lane], wa35 = w2a[35 * 32 + lane];
    float wb[32];
#pragma unroll
    for (int k = 0; k < 32; k++) wb[k] = w2b[k * 32 + lane];
    float bb = b2b[lane];

    float pix = pos[3 * i + 0], piy = pos[3 * i + 1], piz = pos[3 * i + 2];
    float nix = nrm[3 * i + 0], niy = nrm[3 * i + 1], niz = nrm[3 * i + 2];

    int j = (lane < KNN) ? g_knn[i * KNN + lane] : i;
    float pjx = pos[3 * j + 0], pjy = pos[3 * j + 1], pjz = pos[3 * j + 2];
    float njx = nrm[3 * j + 0], njy = nrm[3 * j + 1], njz = nrm[3 * j + 2];

    float px = pjx - pix, py = pjy - piy, pz = pjz - piz;
    float f0 = safe_norm3(px, py, pz);
    float f1 = angle3(nix, niy, niz, px, py, pz);
    float f2 = angle3(njx, njy, njz, px, py, pz);
    float f3 = angle3(nix, niy, niz, njx, njy, njz);
    if (lane < 17) { sf[warp][lane] = make_float4(f0, f1, f2, f3); si[warp][lane] = j; }
    __syncwarp();

    float yv[17];
#pragma unroll
    for (int e = 0; e < 17; e++)
        yv[e] = g_y[si[warp][e] * CH + lane];

#pragma unroll
    for (int e = 0; e < 17; e++) {
        float4 f = sf[warp][e];
        float h = yv[e];
        h = fmaf(f.x, wa32, h); h = fmaf(f.y, wa33, h);
        h = fmaf(f.z, wa34, h); h = fmaf(f.w, wa35, h);
        sh[warp][e][lane] = fmaxf(h, 0.f);
    }
    __syncwarp();

    float best = -CUDART_INF_F;
    for (int e = 0; e < 17; e++) {
        float o0 = bb, o1 = 0.f, o2 = 0.f, o3 = 0.f;
        const float4* hv4 = (const float4*)sh[warp][e];
#pragma unroll
        for (int m = 0; m < 8; m++) {
            float4 hv = hv4[m];
            o0 = fmaf(hv.x, wb[4 * m + 0], o0);
            o1 = fmaf(hv.y, wb[4 * m + 1], o1);
            o2 = fmaf(hv.z, wb[4 * m + 2], o2);
            o3 = fmaf(hv.w, wb[4 * m + 3], o3);
        }
        best = fmaxf(best, (o0 + o1) + (o2 + o3));
    }
    red[warp][lane] = fmaxf(best, 0.f);
    __syncthreads();

    if (warp == 0) {
        float m = red[0][lane];
#pragma unroll
        for (int r = 1; r < 8; r++) m = fmaxf(m, red[r][lane]);
        int b = (blockIdx.x * 8) >> 12;
        atomicMax((int*)&g_pool[b * CH + lane], __float_as_int(m));
    }
}

__global__ void fc_kernel(const float* __restrict__ wc,
                          const float* __restrict__ bc,
                          float* __restrict__ out) {
    int t = threadIdx.x;
    if (t < NB * NCLS) {
        int b = t / NCLS, o = t % NCLS;
        float acc = bc[o];
#pragma unroll
        for (int c = 0; c < CH; c++)
            acc = fmaf(g_pool[b * CH + c], wc[c * NCLS + o], acc);
        out[t] = acc;
    }
}

extern "C" void kernel_launch(void* const* d_in, const int* in_sizes, int n_in,
                              void* d_out, int out_size) {
    const float* pos = (const float*)d_in[0];
    const float* nrm = (const float*)d_in[1];
    const float* w1a = (const float*)d_in[3];
    const float* b1a = (const float*)d_in[4];
    const float* w1b = (const float*)d_in[5];
    const float* b1b = (const float*)d_in[6];
    const float* w2a = (const float*)d_in[7];
    const float* b2a = (const float*)d_in[8];
    const float* w2b = (const float*)d_in[9];
    const float* b2b = (const float*)d_in[10];
    const float* wc  = (const float*)d_in[11];
    const float* bc  = (const float*)d_in[12];
    float* out = (float*)d_out;

    prep_kernel<<<MPTS / 512, 256>>>(pos, 0);
    prep_kernel<<<MPTS / 512, 256>>>(pos, MPTS / 2);
    pool_init_kernel<<<1, 256>>>();
    knn_kernel<<<MPTS / 16, 256>>>();                 // 4th launch (ncu sample)
    conv1_kernel<<<MPTS / 8, 256>>>(pos, nrm, w1a, b1a, w1b, b1b, w2a, b2a);
    conv2_kernel<<<MPTS / 8, 256>>>(pos, nrm, w2a, w2b, b2b);
    fc_kernel<<<1, 320>>>(wc, bc, out);
}